// round 4
// baseline (speedup 1.0000x reference)
#include <cuda_runtime.h>
#include <cstdint>

#define BB 64
#define HH 512
#define WW 512
#define NBOX 160
#define SLABS 8
#define SLAB_ROWS 64   // HH / SLABS
#define THREADS 256
#define NUNITS (BB * SLABS)   // 512 work units, one per CTA

// Per-unit partials: fully overwritten every launch (no zeroing needed).
__device__ float g_all[NUNITS];
__device__ float g_pnt[NUNITS];
__device__ int   g_cnt[NUNITS];
__device__ int   g_ticket = 0;

// bits [p, q), 0 <= p < q <= 64
__device__ __forceinline__ unsigned long long rmask64(int p, int q) {
    int n = q - p;
    return (~0ull >> (64 - n)) << p;
}

__device__ __forceinline__ float sigmoidf(float x) {
    return __fdividef(1.f, 1.f + __expf(-x));
}

__global__ __launch_bounds__(THREADS, 4)
void motion_mask_fused(const float* __restrict__ pred,
                       const int*   __restrict__ tgt,
                       float*       __restrict__ out) {
    __shared__ int s_nact;
    __shared__ unsigned long long s_rm[NBOX];  // row mask within slab
    __shared__ int2 s_y[NBOX];                 // [y1, y2) column interval

    const int tid  = threadIdx.x;
    const int slab = blockIdx.x;               // 0..7
    const int b    = blockIdx.y;               // 0..63
    const int r0   = slab * SLAB_ROWS;

    if (tid == 0) s_nact = 0;
    __syncthreads();

    // ---- compact boxes intersecting this slab; precompute 64-row bitmasks ----
    if (tid < NBOX) {
        int4 t4 = ((const int4*)tgt)[b * NBOX + tid];   // (x, y, sx, sy)
        int x1 = min(t4.x, HH);
        int x2 = min(t4.x + t4.z, HH);
        int y1 = min(t4.y, WW);
        int y2 = min(t4.y + t4.w, WW);
        int a = max(x1 - r0, 0);
        int e = min(x2 - r0, SLAB_ROWS);
        if (e > a && y2 > y1) {
            int pos = atomicAdd(&s_nact, 1);
            s_rm[pos] = rmask64(a, e);
            s_y[pos]  = make_int2(y1, y2);
        }
    }
    __syncthreads();
    const int nact = s_nact;

    // ---- thread layout: 128 threads x 4 columns, 2 row-halves of 32 rows ----
    const int half = tid >> 7;         // 0 or 1
    const int ct   = tid & 127;
    const int c0   = ct * 4;

    uint32_t mm0 = 0, mm1 = 0, mm2 = 0, mm3 = 0;
    for (int j = 0; j < nact; j++) {
        int2 yy = s_y[j];
        uint32_t rm32 = (uint32_t)(s_rm[j] >> (half * 32));
        if (yy.x <= c0     && c0     < yy.y) mm0 |= rm32;
        if (yy.x <= c0 + 1 && c0 + 1 < yy.y) mm1 |= rm32;
        if (yy.x <= c0 + 2 && c0 + 2 < yy.y) mm2 |= rm32;
        if (yy.x <= c0 + 3 && c0 + 3 < yy.y) mm3 |= rm32;
    }
    int cnt = __popc(mm0) + __popc(mm1) + __popc(mm2) + __popc(mm3);

    // ---- pixel loop: float4 loads, sigmoid, masked accumulation ----
    const float* base = pred + (size_t)b * HH * WW
                             + (size_t)(r0 + half * 32) * WW + c0;
    float s_all = 0.f, s_pnt = 0.f;
#pragma unroll 8
    for (int rr = 0; rr < 32; rr++) {
        float4 v = *(const float4*)(base + (size_t)rr * WW);
        float sg0 = sigmoidf(v.x);
        float sg1 = sigmoidf(v.y);
        float sg2 = sigmoidf(v.z);
        float sg3 = sigmoidf(v.w);
        s_all += (sg0 + sg1) + (sg2 + sg3);
        s_pnt += ((mm0 >> rr) & 1u) ? sg0 : 0.f;
        s_pnt += ((mm1 >> rr) & 1u) ? sg1 : 0.f;
        s_pnt += ((mm2 >> rr) & 1u) ? sg2 : 0.f;
        s_pnt += ((mm3 >> rr) & 1u) ? sg3 : 0.f;
    }

    // ---- block reduction ----
#pragma unroll
    for (int o = 16; o; o >>= 1) {
        s_all += __shfl_down_sync(0xFFFFFFFFu, s_all, o);
        s_pnt += __shfl_down_sync(0xFFFFFFFFu, s_pnt, o);
        cnt   += __shfl_down_sync(0xFFFFFFFFu, cnt, o);
    }
    __shared__ float w_all[THREADS / 32], w_pnt[THREADS / 32];
    __shared__ int   w_cnt[THREADS / 32];
    const int lane = tid & 31, warp = tid >> 5;
    if (lane == 0) { w_all[warp] = s_all; w_pnt[warp] = s_pnt; w_cnt[warp] = cnt; }
    __syncthreads();

    __shared__ bool s_isLast;
    if (tid == 0) {
        float ta = 0.f, tp = 0.f; int tc = 0;
#pragma unroll
        for (int i = 0; i < THREADS / 32; i++) { ta += w_all[i]; tp += w_pnt[i]; tc += w_cnt[i]; }
        const int u = b * SLABS + slab;
        g_all[u] = ta;
        g_pnt[u] = tp;
        g_cnt[u] = tc;
        __threadfence();
        int t = atomicAdd(&g_ticket, 1);
        s_isLast = (t == NUNITS - 1);
    }
    __syncthreads();

    // ---- last CTA finalizes (deterministic order, double precision) ----
    if (s_isLast) {
        __threadfence();  // acquire: make all units' stores visible
        __shared__ double s_loss[BB];
        if (tid < BB) {
            double S = 0.0, P = 0.0; long long C = 0;
#pragma unroll
            for (int i = 0; i < SLABS; i++) {
                int u = tid * SLABS + i;
                S += (double)g_all[u];
                P += (double)g_pnt[u];
                C += (long long)g_cnt[u];
            }
            double T = 255.0 * (double)C;   // target_sum
            double I = 255.0 * P;           // intersection
            s_loss[tid] = (I + 1.0) / (S + T - I + 1.0);
        }
        __syncthreads();
        if (tid == 0) {
            double acc = 0.0;
            for (int i = 0; i < BB; i++) acc += s_loss[i];
            out[0] = (float)(1.0 - acc / (double)BB);
            g_ticket = 0;   // reset for next graph replay
        }
    }
}

extern "C" void kernel_launch(void* const* d_in, const int* in_sizes, int n_in,
                              void* d_out, int out_size) {
    const float* pred = (const float*)d_in[0];   // pred_m  f32 (64,1,512,512)
    const int*   tgt  = (const int*)d_in[1];     // multi_targets i32 (64,5,32,4)
    float* out = (float*)d_out;

    dim3 grid(SLABS, BB);
    motion_mask_fused<<<grid, THREADS>>>(pred, tgt, out);
}

// round 6
// speedup vs baseline: 1.1695x; 1.1695x over previous
#include <cuda_runtime.h>
#include <cstdint>

#define BB 64
#define HH 512
#define WW 512
#define NBOX 160
#define SLABS 8
#define SLAB_ROWS 64   // HH / SLABS
#define THREADS 256
#define NUNITS (BB * SLABS)   // 512 work units, one per CTA

// Per-unit partials: fully overwritten every launch (no zeroing needed).
__device__ float g_all[NUNITS];
__device__ float g_pnt[NUNITS];
__device__ int   g_cnt[NUNITS];
__device__ int   g_ticket = 0;

// bits [p, q), 0 <= p < q <= 64
__device__ __forceinline__ unsigned long long rmask64(int p, int q) {
    int n = q - p;
    return (~0ull >> (64 - n)) << p;
}

__device__ __forceinline__ float sigmoidf(float x) {
    return __fdividef(1.f, 1.f + __expf(-x));
}

__global__ __launch_bounds__(THREADS, 4)
void motion_mask_fused(const float* __restrict__ pred,
                       const int*   __restrict__ tgt,
                       float*       __restrict__ out) {
    // Per-column 64-row coverage masks for this slab, split lo/hi 32 rows.
    __shared__ alignas(16) uint32_t cm_lo[WW];
    __shared__ alignas(16) uint32_t cm_hi[WW];

    const int tid  = threadIdx.x;
    const int slab = blockIdx.x;               // 0..7
    const int b    = blockIdx.y;               // 0..63
    const int r0   = slab * SLAB_ROWS;
    const int lane = tid & 31, warp = tid >> 5;

    // ---- init column masks ----
    cm_lo[tid] = 0u; cm_lo[tid + 256] = 0u;
    cm_hi[tid] = 0u; cm_hi[tid + 256] = 0u;
    __syncthreads();

    // ---- cooperative box scatter: warp w handles boxes w, w+8, ... ----
    const int4* tgt4 = (const int4*)tgt + (size_t)b * NBOX;
    for (int j = warp; j < NBOX; j += THREADS / 32) {
        int4 t4 = tgt4[j];                     // uniform per warp (broadcast)
        int x1 = min(t4.x, HH);
        int x2 = min(t4.x + t4.z, HH);
        int y1 = min(t4.y, WW);
        int y2 = min(t4.y + t4.w, WW);
        int a = max(x1 - r0, 0);
        int e = min(x2 - r0, SLAB_ROWS);
        if (e > a && y2 > y1) {
            unsigned long long rm = rmask64(a, e);
            uint32_t lo = (uint32_t)rm;
            uint32_t hi = (uint32_t)(rm >> 32);
            if (lo) for (int c = y1 + lane; c < y2; c += 32) atomicOr(&cm_lo[c], lo);
            if (hi) for (int c = y1 + lane; c < y2; c += 32) atomicOr(&cm_hi[c], hi);
        }
    }
    __syncthreads();

    // ---- thread layout: 128 threads x 4 columns, 2 row-halves of 32 rows ----
    const int half = tid >> 7;                 // 0 = rows 0..31, 1 = rows 32..63
    const int ct   = tid & 127;
    const int c0   = ct * 4;

    uint4 m4 = half ? *(const uint4*)&cm_hi[c0] : *(const uint4*)&cm_lo[c0];
    const uint32_t mm0 = m4.x, mm1 = m4.y, mm2 = m4.z, mm3 = m4.w;
    int cnt = __popc(mm0) + __popc(mm1) + __popc(mm2) + __popc(mm3);

    // ---- pixel loop: float4 loads, sigmoid, constant-mask predicated adds ----
    const float* base = pred + (size_t)b * HH * WW
                             + (size_t)(r0 + half * 32) * WW + c0;
    float s_all = 0.f, s_pnt = 0.f;
#pragma unroll
    for (int rr = 0; rr < 32; rr++) {
        float4 v = *(const float4*)(base + (size_t)rr * WW);
        float sg0 = sigmoidf(v.x);
        float sg1 = sigmoidf(v.y);
        float sg2 = sigmoidf(v.z);
        float sg3 = sigmoidf(v.w);
        s_all += (sg0 + sg1) + (sg2 + sg3);
        const uint32_t bit = 1u << rr;         // compile-time constant per body
        if (mm0 & bit) s_pnt += sg0;
        if (mm1 & bit) s_pnt += sg1;
        if (mm2 & bit) s_pnt += sg2;
        if (mm3 & bit) s_pnt += sg3;
    }

    // ---- block reduction ----
#pragma unroll
    for (int o = 16; o; o >>= 1) {
        s_all += __shfl_down_sync(0xFFFFFFFFu, s_all, o);
        s_pnt += __shfl_down_sync(0xFFFFFFFFu, s_pnt, o);
        cnt   += __shfl_down_sync(0xFFFFFFFFu, cnt, o);
    }
    __shared__ float w_all[THREADS / 32], w_pnt[THREADS / 32];
    __shared__ int   w_cnt[THREADS / 32];
    if (lane == 0) { w_all[warp] = s_all; w_pnt[warp] = s_pnt; w_cnt[warp] = cnt; }
    __syncthreads();

    __shared__ bool s_isLast;
    if (tid == 0) {
        float ta = 0.f, tp = 0.f; int tc = 0;
#pragma unroll
        for (int i = 0; i < THREADS / 32; i++) { ta += w_all[i]; tp += w_pnt[i]; tc += w_cnt[i]; }
        const int u = b * SLABS + slab;
        g_all[u] = ta;
        g_pnt[u] = tp;
        g_cnt[u] = tc;
        __threadfence();
        int t = atomicAdd(&g_ticket, 1);
        s_isLast = (t == NUNITS - 1);
    }
    __syncthreads();

    // ---- last CTA finalizes (deterministic order, double precision) ----
    if (s_isLast) {
        __threadfence();  // acquire: make all units' stores visible
        __shared__ double s_loss[BB];
        if (tid < BB) {
            double S = 0.0, P = 0.0; long long C = 0;
#pragma unroll
            for (int i = 0; i < SLABS; i++) {
                int u = tid * SLABS + i;
                S += (double)g_all[u];
                P += (double)g_pnt[u];
                C += (long long)g_cnt[u];
            }
            double T = 255.0 * (double)C;   // target_sum
            double I = 255.0 * P;           // intersection
            s_loss[tid] = (I + 1.0) / (S + T - I + 1.0);
        }
        __syncthreads();
        if (tid == 0) {
            double acc = 0.0;
            for (int i = 0; i < BB; i++) acc += s_loss[i];
            out[0] = (float)(1.0 - acc / (double)BB);
            g_ticket = 0;   // reset for next graph replay
        }
    }
}

extern "C" void kernel_launch(void* const* d_in, const int* in_sizes, int n_in,
                              void* d_out, int out_size) {
    const float* pred = (const float*)d_in[0];   // pred_m  f32 (64,1,512,512)
    const int*   tgt  = (const int*)d_in[1];     // multi_targets i32 (64,5,32,4)
    float* out = (float*)d_out;

    dim3 grid(SLABS, BB);
    motion_mask_fused<<<grid, THREADS>>>(pred, tgt, out);
}

// round 7
// speedup vs baseline: 1.2897x; 1.1028x over previous
#include <cuda_runtime.h>
#include <cstdint>

#define BB 64
#define HH 512
#define WW 512
#define NBOX 160
#define SLABS 8
#define SLAB_ROWS 64   // HH / SLABS
#define THREADS 256
#define NUNITS (BB * SLABS)   // 512 work units, one per CTA
#define NTILES 16             // 16 column tiles of 32 cols each

// Per-unit partials: fully overwritten every launch (no zeroing needed).
__device__ float g_all[NUNITS];
__device__ float g_pnt[NUNITS];
__device__ int   g_cnt[NUNITS];
__device__ int   g_ticket = 0;

// bits [p, q), 0 <= p < q <= 64
__device__ __forceinline__ unsigned long long rmask64(int p, int q) {
    int n = q - p;
    return (~0ull >> (64 - n)) << p;
}

__device__ __forceinline__ float sigmoidf(float x) {
    return __fdividef(1.f, 1.f + __expf(-x));
}

__global__ __launch_bounds__(THREADS, 4)
void motion_mask_fused(const float* __restrict__ pred,
                       const int*   __restrict__ tgt,
                       float*       __restrict__ out) {
    // Per-column-tile box lists (a box appears in every 32-col tile it overlaps).
    __shared__ int      s_cnt[NTILES];
    __shared__ uint32_t s_lo[NTILES * NBOX];   // rows 0..31 mask
    __shared__ uint32_t s_hi[NTILES * NBOX];   // rows 32..63 mask
    __shared__ uint32_t s_yy[NTILES * NBOX];   // y1 | (y2 << 16)

    const int tid  = threadIdx.x;
    const int slab = blockIdx.x;               // 0..7
    const int b    = blockIdx.y;               // 0..63
    const int r0   = slab * SLAB_ROWS;
    const int lane = tid & 31, warp = tid >> 5;

    if (tid < NTILES) s_cnt[tid] = 0;
    __syncthreads();

    // ---- bin boxes into column tiles (O(incidences), ~300 pushes/CTA) ----
    if (tid < NBOX) {
        int4 t4 = ((const int4*)tgt)[b * NBOX + tid];   // (x, y, sx, sy)
        int x1 = min(t4.x, HH);
        int x2 = min(t4.x + t4.z, HH);
        int y1 = min(t4.y, WW);
        int y2 = min(t4.y + t4.w, WW);
        int a = max(x1 - r0, 0);
        int e = min(x2 - r0, SLAB_ROWS);
        if (e > a && y2 > y1) {
            unsigned long long rm = rmask64(a, e);
            uint32_t lo = (uint32_t)rm;
            uint32_t hi = (uint32_t)(rm >> 32);
            uint32_t yy = (uint32_t)y1 | ((uint32_t)y2 << 16);
            int t1 = y1 >> 5, t2 = (y2 - 1) >> 5;
            for (int t = t1; t <= t2; t++) {
                int pos = atomicAdd(&s_cnt[t], 1);
                int idx = t * NBOX + pos;
                s_lo[idx] = lo;
                s_hi[idx] = hi;
                s_yy[idx] = yy;
            }
        }
    }
    __syncthreads();

    // ---- thread layout: 128 threads x 4 columns, 2 row-halves of 32 rows ----
    const int half = tid >> 7;                 // 0 = rows 0..31, 1 = rows 32..63
    const int ct   = tid & 127;
    const int c0   = ct * 4;
    const int tile = ct >> 3;                  // 32-col tile containing c0..c0+3
    const uint32_t* mrow = half ? s_hi : s_lo;

    uint32_t mm0 = 0, mm1 = 0, mm2 = 0, mm3 = 0;
    {
        const int n    = s_cnt[tile];
        const int base = tile * NBOX;
        for (int j = 0; j < n; j++) {
            uint32_t yy = s_yy[base + j];
            uint32_t m  = mrow[base + j];
            int y1 = (int)(yy & 0xFFFFu);
            int y2 = (int)(yy >> 16);
            if (y1 <= c0     && c0     < y2) mm0 |= m;
            if (y1 <= c0 + 1 && c0 + 1 < y2) mm1 |= m;
            if (y1 <= c0 + 2 && c0 + 2 < y2) mm2 |= m;
            if (y1 <= c0 + 3 && c0 + 3 < y2) mm3 |= m;
        }
    }
    int cnt = __popc(mm0) + __popc(mm1) + __popc(mm2) + __popc(mm3);

    // ---- pixel loop: float4 loads, sigmoid, constant-bit predicated adds ----
    const float* base = pred + (size_t)b * HH * WW
                             + (size_t)(r0 + half * 32) * WW + c0;
    float s_all = 0.f, s_pnt = 0.f;
#pragma unroll
    for (int rr = 0; rr < 32; rr++) {
        float4 v = *(const float4*)(base + (size_t)rr * WW);
        float sg0 = sigmoidf(v.x);
        float sg1 = sigmoidf(v.y);
        float sg2 = sigmoidf(v.z);
        float sg3 = sigmoidf(v.w);
        s_all += (sg0 + sg1) + (sg2 + sg3);
        const uint32_t bit = 1u << rr;         // compile-time constant per body
        if (mm0 & bit) s_pnt += sg0;
        if (mm1 & bit) s_pnt += sg1;
        if (mm2 & bit) s_pnt += sg2;
        if (mm3 & bit) s_pnt += sg3;
    }

    // ---- block reduction ----
#pragma unroll
    for (int o = 16; o; o >>= 1) {
        s_all += __shfl_down_sync(0xFFFFFFFFu, s_all, o);
        s_pnt += __shfl_down_sync(0xFFFFFFFFu, s_pnt, o);
        cnt   += __shfl_down_sync(0xFFFFFFFFu, cnt, o);
    }
    __shared__ float w_all[THREADS / 32], w_pnt[THREADS / 32];
    __shared__ int   w_cnt[THREADS / 32];
    if (lane == 0) { w_all[warp] = s_all; w_pnt[warp] = s_pnt; w_cnt[warp] = cnt; }
    __syncthreads();

    __shared__ bool s_isLast;
    if (tid == 0) {
        float ta = 0.f, tp = 0.f; int tc = 0;
#pragma unroll
        for (int i = 0; i < THREADS / 32; i++) { ta += w_all[i]; tp += w_pnt[i]; tc += w_cnt[i]; }
        const int u = b * SLABS + slab;
        g_all[u] = ta;
        g_pnt[u] = tp;
        g_cnt[u] = tc;
        __threadfence();
        int t = atomicAdd(&g_ticket, 1);
        s_isLast = (t == NUNITS - 1);
    }
    __syncthreads();

    // ---- last CTA finalizes (deterministic order, double precision) ----
    if (s_isLast) {
        __threadfence();  // acquire: make all units' stores visible
        __shared__ double s_loss[BB];
        if (tid < BB) {
            double S = 0.0, P = 0.0; long long C = 0;
#pragma unroll
            for (int i = 0; i < SLABS; i++) {
                int u = tid * SLABS + i;
                S += (double)g_all[u];
                P += (double)g_pnt[u];
                C += (long long)g_cnt[u];
            }
            double T = 255.0 * (double)C;   // target_sum
            double I = 255.0 * P;           // intersection
            s_loss[tid] = (I + 1.0) / (S + T - I + 1.0);
        }
        __syncthreads();
        if (tid == 0) {
            double acc = 0.0;
            for (int i = 0; i < BB; i++) acc += s_loss[i];
            out[0] = (float)(1.0 - acc / (double)BB);
            g_ticket = 0;   // reset for next graph replay
        }
    }
}

extern "C" void kernel_launch(void* const* d_in, const int* in_sizes, int n_in,
                              void* d_out, int out_size) {
    const float* pred = (const float*)d_in[0];   // pred_m  f32 (64,1,512,512)
    const int*   tgt  = (const int*)d_in[1];     // multi_targets i32 (64,5,32,4)
    float* out = (float*)d_out;

    dim3 grid(SLABS, BB);
    motion_mask_fused<<<grid, THREADS>>>(pred, tgt, out);
}

// round 8
// speedup vs baseline: 1.5186x; 1.1774x over previous
#include <cuda_runtime.h>
#include <cstdint>

#define BB 64
#define HH 512
#define WW 512
#define NBOX 160
#define SLABS 16
#define SLAB_ROWS 32   // HH / SLABS
#define THREADS 128
#define NUNITS (BB * SLABS)   // 1024 work units, one per CTA
#define NTILES 16             // 16 column tiles of 32 cols each

// Per-unit partials: fully overwritten every launch (no zeroing needed).
__device__ float g_all[NUNITS];
__device__ float g_pnt[NUNITS];
__device__ int   g_cnt[NUNITS];
__device__ int   g_ticket = 0;

// bits [p, q), 0 <= p < q <= 32
__device__ __forceinline__ uint32_t rmask32(int p, int q) {
    int n = q - p;
    return (0xFFFFFFFFu >> (32 - n)) << p;
}

__device__ __forceinline__ float sigmoidf(float x) {
    return __fdividef(1.f, 1.f + __expf(-x));
}

__global__ __launch_bounds__(THREADS, 10)
void motion_mask_fused(const float* __restrict__ pred,
                       const int*   __restrict__ tgt,
                       float*       __restrict__ out) {
    // Per-column-tile box lists: entry = (rowmask, y1 | len<<16)
    __shared__ int   s_cnt[NTILES];
    __shared__ uint2 s_box[NTILES * NBOX];

    const int tid  = threadIdx.x;
    const int slab = blockIdx.x;               // 0..15
    const int b    = blockIdx.y;               // 0..63
    const int r0   = slab * SLAB_ROWS;
    const int lane = tid & 31, warp = tid >> 5;

    if (tid < NTILES) s_cnt[tid] = 0;
    __syncthreads();

    // ---- bin boxes into 32-col tiles (O(incidences)) ----
    for (int j = tid; j < NBOX; j += THREADS) {
        int4 t4 = ((const int4*)tgt)[b * NBOX + j];   // (x, y, sx, sy)
        int x1 = min(t4.x, HH);
        int x2 = min(t4.x + t4.z, HH);
        int y1 = min(t4.y, WW);
        int y2 = min(t4.y + t4.w, WW);
        int a = max(x1 - r0, 0);
        int e = min(x2 - r0, SLAB_ROWS);
        if (e > a && y2 > y1) {
            uint32_t rm   = rmask32(a, e);
            uint32_t pack = (uint32_t)y1 | ((uint32_t)(y2 - y1) << 16);
            int t1 = y1 >> 5, t2 = (y2 - 1) >> 5;
            for (int t = t1; t <= t2; t++) {
                int pos = atomicAdd(&s_cnt[t], 1);
                s_box[t * NBOX + pos] = make_uint2(rm, pack);
            }
        }
    }
    __syncthreads();

    // ---- thread layout: 128 threads x 4 columns x 32 rows ----
    const int c0   = tid * 4;
    const int tile = tid >> 3;

    uint32_t mm0 = 0, mm1 = 0, mm2 = 0, mm3 = 0;
    {
        const int n    = s_cnt[tile];
        const int base = tile * NBOX;
        for (int j = 0; j < n; j++) {
            uint2 e = s_box[base + j];
            uint32_t y1  = e.y & 0xFFFFu;
            uint32_t len = e.y >> 16;
            if ((uint32_t)(c0     - y1) < len) mm0 |= e.x;
            if ((uint32_t)(c0 + 1 - y1) < len) mm1 |= e.x;
            if ((uint32_t)(c0 + 2 - y1) < len) mm2 |= e.x;
            if ((uint32_t)(c0 + 3 - y1) < len) mm3 |= e.x;
        }
    }
    int cnt = __popc(mm0) + __popc(mm1) + __popc(mm2) + __popc(mm3);

    // ---- pixel loop: float4 loads, sigmoid, constant-bit predicated adds ----
    const float* base = pred + (size_t)b * HH * WW + (size_t)r0 * WW + c0;
    float s_all = 0.f, s_pnt = 0.f;
#pragma unroll
    for (int rr = 0; rr < SLAB_ROWS; rr++) {
        float4 v = *(const float4*)(base + (size_t)rr * WW);
        float sg0 = sigmoidf(v.x);
        float sg1 = sigmoidf(v.y);
        float sg2 = sigmoidf(v.z);
        float sg3 = sigmoidf(v.w);
        s_all += (sg0 + sg1) + (sg2 + sg3);
        const uint32_t bit = 1u << rr;         // compile-time constant per body
        if (mm0 & bit) s_pnt += sg0;
        if (mm1 & bit) s_pnt += sg1;
        if (mm2 & bit) s_pnt += sg2;
        if (mm3 & bit) s_pnt += sg3;
    }

    // ---- block reduction (4 warps) ----
#pragma unroll
    for (int o = 16; o; o >>= 1) {
        s_all += __shfl_down_sync(0xFFFFFFFFu, s_all, o);
        s_pnt += __shfl_down_sync(0xFFFFFFFFu, s_pnt, o);
        cnt   += __shfl_down_sync(0xFFFFFFFFu, cnt, o);
    }
    __shared__ float w_all[THREADS / 32], w_pnt[THREADS / 32];
    __shared__ int   w_cnt[THREADS / 32];
    if (lane == 0) { w_all[warp] = s_all; w_pnt[warp] = s_pnt; w_cnt[warp] = cnt; }
    __syncthreads();

    __shared__ bool s_isLast;
    if (tid == 0) {
        float ta = 0.f, tp = 0.f; int tc = 0;
#pragma unroll
        for (int i = 0; i < THREADS / 32; i++) { ta += w_all[i]; tp += w_pnt[i]; tc += w_cnt[i]; }
        const int u = b * SLABS + slab;
        g_all[u] = ta;
        g_pnt[u] = tp;
        g_cnt[u] = tc;
        __threadfence();
        int t = atomicAdd(&g_ticket, 1);
        s_isLast = (t == NUNITS - 1);
    }
    __syncthreads();

    // ---- last CTA finalizes (deterministic order, double precision) ----
    if (s_isLast) {
        __threadfence();  // acquire: make all units' stores visible
        __shared__ double s_loss[BB];
        if (tid < BB) {
            double S = 0.0, P = 0.0; long long C = 0;
#pragma unroll
            for (int i = 0; i < SLABS; i++) {
                int u = tid * SLABS + i;
                S += (double)g_all[u];
                P += (double)g_pnt[u];
                C += (long long)g_cnt[u];
            }
            double T = 255.0 * (double)C;   // target_sum
            double I = 255.0 * P;           // intersection
            s_loss[tid] = (I + 1.0) / (S + T - I + 1.0);
        }
        __syncthreads();
        if (tid == 0) {
            double acc = 0.0;
            for (int i = 0; i < BB; i++) acc += s_loss[i];
            out[0] = (float)(1.0 - acc / (double)BB);
            g_ticket = 0;   // reset for next graph replay
        }
    }
}

extern "C" void kernel_launch(void* const* d_in, const int* in_sizes, int n_in,
                              void* d_out, int out_size) {
    const float* pred = (const float*)d_in[0];   // pred_m  f32 (64,1,512,512)
    const int*   tgt  = (const int*)d_in[1];     // multi_targets i32 (64,5,32,4)
    float* out = (float*)d_out;

    dim3 grid(SLABS, BB);
    motion_mask_fused<<<grid, THREADS>>>(pred, tgt, out);
}